// round 4
// baseline (speedup 1.0000x reference)
#include <cuda_runtime.h>
#include <cuda_bf16.h>

#define B_    128
#define H_    14
#define W_    14
#define C_    512
#define C4_   128           // C/4
#define NCLS_ 200
#define HWN_  196
#define TILE_ 28
#define NT_   7
#define TSTR_ 132           // tile row stride (floats); 132*4=528 B, 16B-multiple

// block: 8 warps; warp w = hw-group w; lane = float4 channel-group (32 -> 128 ch)
__global__ __launch_bounds__(256)
void fused_kernel(const float* __restrict__ x,
                  const float* __restrict__ gt,
                  const float* __restrict__ t_p,
                  const float* __restrict__ ct,
                  float* __restrict__ out) {
    __shared__ float4 sv4[256];
    __shared__ int4   si4[256];
    __shared__ int    s_plane[128];          // per local channel: t_p plane offset
    __shared__ int    s_cls;
    __shared__ __align__(16) float smem_t[TILE_ * TSTR_];   // 14.8 KB

    const int tid  = threadIdx.x;
    const int lane = tid & 31;               // channel group within block
    const int hwg  = tid >> 5;               // hw group == warp id
    const int b    = blockIdx.y;
    const int c4   = blockIdx.x * 32 + lane; // float4 column, 0..127

    const float4* x4 = (const float4*)x;
    const size_t bb4 = (size_t)b * HWN_ * C4_;

    // ---- cls[b] = argmax(gt[b,:200]) — every warp redundantly (cheap) ----
    {
        const float* g = gt + (size_t)b * NCLS_;
        float bv = -1e30f; int bi = NCLS_;
        for (int i = lane; i < NCLS_; i += 32) {
            float v = __ldg(g + i);
            if (v > bv) { bv = v; bi = i; }
        }
        #pragma unroll
        for (int s = 16; s > 0; s >>= 1) {
            float ov = __shfl_down_sync(0xffffffffu, bv, s);
            int   oi = __shfl_down_sync(0xffffffffu, bi, s);
            if (ov > bv || (ov == bv && oi < bi)) { bv = ov; bi = oi; }
        }
        if (lane == 0) s_cls = bi;
    }

    // ---- phase 1: spatial argmax, 4 channels per thread, hw interleaved ----
    float mv[4] = {-1e30f, -1e30f, -1e30f, -1e30f};
    int   mi[4] = {0, 0, 0, 0};
    for (int hw = hwg; hw < HWN_; hw += 8) {
        float4 v = __ldg(&x4[bb4 + (size_t)hw * C4_ + c4]);
        if (v.x > mv[0]) { mv[0] = v.x; mi[0] = hw; }
        if (v.y > mv[1]) { mv[1] = v.y; mi[1] = hw; }
        if (v.z > mv[2]) { mv[2] = v.z; mi[2] = hw; }
        if (v.w > mv[3]) { mv[3] = v.w; mi[3] = hw; }
    }
    sv4[tid] = make_float4(mv[0], mv[1], mv[2], mv[3]);
    si4[tid] = make_int4(mi[0], mi[1], mi[2], mi[3]);
    __syncthreads();

    if (tid < 32) {
        float bm[4]; int bx[4];
        float4 v0 = sv4[tid]; int4 i0 = si4[tid];
        bm[0]=v0.x; bm[1]=v0.y; bm[2]=v0.z; bm[3]=v0.w;
        bx[0]=i0.x; bx[1]=i0.y; bx[2]=i0.z; bx[3]=i0.w;
        #pragma unroll
        for (int g2 = 1; g2 < 8; ++g2) {
            float4 v = sv4[g2 * 32 + tid];
            int4   i = si4[g2 * 32 + tid];
            if (v.x > bm[0] || (v.x == bm[0] && i.x < bx[0])) { bm[0]=v.x; bx[0]=i.x; }
            if (v.y > bm[1] || (v.y == bm[1] && i.y < bx[1])) { bm[1]=v.y; bx[1]=i.y; }
            if (v.z > bm[2] || (v.z == bm[2] && i.z < bx[2])) { bm[2]=v.z; bx[2]=i.z; }
            if (v.w > bm[3] || (v.w == bm[3] && i.w < bx[3])) { bm[3]=v.w; bx[3]=i.w; }
        }
        #pragma unroll
        for (int i = 0; i < 4; ++i) {
            int hh = bx[i] / W_;
            int ww = bx[i] - hh * W_;
            if (bm[i] == 0.0f) { hh = H_; ww = W_; }
            s_plane[tid * 4 + i] = (hh * (W_ + 1) + ww) * HWN_;
        }
    }
    __syncthreads();

    // ---- phase 2: tiled, fully vectorized elementwise ----
    const int cls = s_cls;
    const float4* ct4 = (const float4*)ct;
    const size_t ctb4 = (size_t)cls * HWN_ * C4_ + c4;
    const size_t psz4 = (size_t)B_ * HWN_ * C4_;
    float4* o4 = (float4*)out;

    for (int t = 0; t < NT_; ++t) {
        const int hw0 = t * TILE_;

        // stage templates: warp hwg stages channels [hwg*16, hwg*16+16)
        #pragma unroll
        for (int j = 0; j < 16; ++j) {
            int ch = hwg * 16 + j;
            if (lane < TILE_)
                smem_t[lane * TSTR_ + ch] = __ldg(t_p + s_plane[ch] + hw0 + lane);
        }
        __syncthreads();

        for (int k = hwg; k < TILE_; k += 8) {
            const int hw = hw0 + k;
            const size_t off = bb4 + (size_t)hw * C4_ + c4;
            float4 xv = __ldg(&x4[off]);
            float4 cv = __ldg(&ct4[ctb4 + (size_t)hw * C4_]);
            float4 tv = *(const float4*)&smem_t[k * TSTR_ + lane * 4];
            float4 m;
            m.x = fmaxf(xv.x * tv.x, 0.0f) * cv.x;
            m.y = fmaxf(xv.y * tv.y, 0.0f) * cv.y;
            m.z = fmaxf(xv.z * tv.z, 0.0f) * cv.z;
            m.w = fmaxf(xv.w * tv.w, 0.0f) * cv.w;
            o4[off]            = m;
            o4[psz4 + off]     = xv;
            o4[2 * psz4 + off] = tv;
        }
        __syncthreads();
    }
}

extern "C" void kernel_launch(void* const* d_in, const int* in_sizes, int n_in,
                              void* d_out, int out_size) {
    const float* x  = (const float*)d_in[0];
    const float* gt = (const float*)d_in[1];
    const float* tp = (const float*)d_in[2];
    const float* ct = (const float*)d_in[3];
    float* out = (float*)d_out;

    fused_kernel<<<dim3(C4_ / 32, B_), 256>>>(x, gt, tp, ct, out);
}

// round 6
// speedup vs baseline: 1.1432x; 1.1432x over previous
#include <cuda_runtime.h>
#include <cuda_bf16.h>

#define B_    128
#define H_    14
#define W_    14
#define C_    512
#define C4_   128           // C/4
#define NCLS_ 200
#define HWN_  196
#define TILE_ 28
#define NT_   7
#define TSTR_ 132           // tile row stride (floats); 528 B, 16B-multiple
#define THR_  512
#define NWRP_ 16

// block: 16 warps; warp w = hw-group; lane = float4 channel-group (32 -> 128 ch)
__global__ __launch_bounds__(THR_)
void fused_kernel(const float* __restrict__ x,
                  const float* __restrict__ gt,
                  const float* __restrict__ t_p,
                  const float* __restrict__ ct,
                  float* __restrict__ out) {
    __shared__ float4 sv4[THR_];             // 8 KB
    __shared__ int4   si4[THR_];             // 8 KB
    __shared__ int    s_plane[128];
    __shared__ int    s_cls;
    __shared__ __align__(16) float smem_t[TILE_ * TSTR_];   // 14.8 KB

    const int tid  = threadIdx.x;
    const int lane = tid & 31;               // c4 group within block
    const int hwg  = tid >> 5;               // hw group == warp id (0..15)
    const int b    = blockIdx.y;
    const int c4   = blockIdx.x * 32 + lane;

    const float4* x4 = (const float4*)x;
    const size_t bb4 = (size_t)b * HWN_ * C4_;

    // ---- cls[b] = argmax(gt[b,:200]) — every warp redundantly (cheap) ----
    {
        const float* g = gt + (size_t)b * NCLS_;
        float bv = -1e30f; int bi = NCLS_;
        for (int i = lane; i < NCLS_; i += 32) {
            float v = __ldg(g + i);
            if (v > bv) { bv = v; bi = i; }
        }
        #pragma unroll
        for (int s = 16; s > 0; s >>= 1) {
            float ov = __shfl_down_sync(0xffffffffu, bv, s);
            int   oi = __shfl_down_sync(0xffffffffu, bi, s);
            if (ov > bv || (ov == bv && oi < bi)) { bv = ov; bi = oi; }
        }
        if (tid == 0) s_cls = bi;
    }

    // ---- phase 1: spatial argmax; 4 channels/thread, hw interleaved by 16 ----
    float mv[4] = {-1e30f, -1e30f, -1e30f, -1e30f};
    int   mi[4] = {0, 0, 0, 0};
    for (int hw = hwg; hw < HWN_; hw += NWRP_) {
        float4 v = __ldg(&x4[bb4 + (size_t)hw * C4_ + c4]);
        if (v.x > mv[0]) { mv[0] = v.x; mi[0] = hw; }
        if (v.y > mv[1]) { mv[1] = v.y; mi[1] = hw; }
        if (v.z > mv[2]) { mv[2] = v.z; mi[2] = hw; }
        if (v.w > mv[3]) { mv[3] = v.w; mi[3] = hw; }
    }
    sv4[tid] = make_float4(mv[0], mv[1], mv[2], mv[3]);
    si4[tid] = make_int4(mi[0], mi[1], mi[2], mi[3]);
    __syncthreads();

    if (tid < 32) {
        float bm[4] = {-1e30f, -1e30f, -1e30f, -1e30f};
        int   bx[4] = {0, 0, 0, 0};
        #pragma unroll
        for (int g2 = 0; g2 < NWRP_; ++g2) {
            float4 v = sv4[g2 * 32 + tid];
            int4   i = si4[g2 * 32 + tid];
            if (v.x > bm[0] || (v.x == bm[0] && i.x < bx[0])) { bm[0]=v.x; bx[0]=i.x; }
            if (v.y > bm[1] || (v.y == bm[1] && i.y < bx[1])) { bm[1]=v.y; bx[1]=i.y; }
            if (v.z > bm[2] || (v.z == bm[2] && i.z < bx[2])) { bm[2]=v.z; bx[2]=i.z; }
            if (v.w > bm[3] || (v.w == bm[3] && i.w < bx[3])) { bm[3]=v.w; bx[3]=i.w; }
        }
        #pragma unroll
        for (int i = 0; i < 4; ++i) {
            int hh = bx[i] / W_;
            int ww = bx[i] - hh * W_;
            if (bm[i] == 0.0f) { hh = H_; ww = W_; }   // sentinel
            s_plane[tid * 4 + i] = (hh * (W_ + 1) + ww) * HWN_;
        }
    }
    __syncthreads();

    // ---- phase 2: tiled, fully vectorized elementwise ----
    const int cls = s_cls;
    const float4* ct4 = (const float4*)ct;
    const size_t ctb4 = (size_t)cls * HWN_ * C4_ + c4;
    const size_t psz4 = (size_t)B_ * HWN_ * C4_;
    float4* o4 = (float4*)out;

    for (int t = 0; t < NT_; ++t) {
        const int hw0 = t * TILE_;

        // stage templates: warp hwg stages channels [hwg*8, hwg*8+8)
        #pragma unroll
        for (int j = 0; j < 8; ++j) {
            int ch = hwg * 8 + j;
            if (lane < TILE_)
                smem_t[lane * TSTR_ + ch] = __ldg(t_p + s_plane[ch] + hw0 + lane);
        }
        __syncthreads();

        for (int k = hwg; k < TILE_; k += NWRP_) {
            const int hw = hw0 + k;
            const size_t off = bb4 + (size_t)hw * C4_ + c4;
            float4 xv = __ldg(&x4[off]);
            float4 cv = __ldg(&ct4[ctb4 + (size_t)hw * C4_]);
            float4 tv = *(const float4*)&smem_t[k * TSTR_ + lane * 4];
            float4 m;
            m.x = fmaxf(xv.x * tv.x, 0.0f) * cv.x;
            m.y = fmaxf(xv.y * tv.y, 0.0f) * cv.y;
            m.z = fmaxf(xv.z * tv.z, 0.0f) * cv.z;
            m.w = fmaxf(xv.w * tv.w, 0.0f) * cv.w;
            o4[off]            = m;
            o4[psz4 + off]     = xv;
            o4[2 * psz4 + off] = tv;
        }
        __syncthreads();
    }
}

extern "C" void kernel_launch(void* const* d_in, const int* in_sizes, int n_in,
                              void* d_out, int out_size) {
    const float* x  = (const float*)d_in[0];
    const float* gt = (const float*)d_in[1];
    const float* tp = (const float*)d_in[2];
    const float* ct = (const float*)d_in[3];
    float* out = (float*)d_out;

    fused_kernel<<<dim3(C4_ / 32, B_), THR_>>>(x, gt, tp, ct, out);
}